// round 12
// baseline (speedup 1.0000x reference)
#include <cuda_runtime.h>
#include <cuda_fp16.h>
#include <cstdint>

#define BB   8
#define CIN  64
#define CO   128
#define LL   18
#define LV   16
#define HW   1024
#define NH   2

// ---------------- scratch (device globals; no allocation allowed) ----------
__device__ float g_lp[(size_t)9*BB*NH*CO*CO];

__device__ __half g_Qh[(size_t)BB*CO*LL*HW];
__device__ __half g_Ql[(size_t)BB*CO*LL*HW];
__device__ __half g_Kh[(size_t)BB*CO*LL*HW];
__device__ __half g_Kl[(size_t)BB*CO*LL*HW];
__device__ __half g_Vh[(size_t)BB*CO*LV*HW];
__device__ __half g_aH[(size_t)BB*NH*CO*CO];
__device__ __half g_aL[(size_t)BB*NH*CO*CO];

__device__ __half g_hin[(size_t)BB*LL*HW*CIN];
__device__ __half g_lin[(size_t)BB*LL*HW*CIN];
__device__ __half g_hmm[(size_t)BB*LL*HW*CIN];
__device__ __half g_lmm[(size_t)BB*LL*HW*CIN];

// weight images, 32-ci sub-chunks, pitch 40 halves: [sc][co=128][40]
__device__ uint4 g_wqh[18*640], g_wql[18*640];
__device__ uint4 g_wkh[18*640], g_wkl[18*640];
__device__ uint4 g_wvh[54*640], g_wvl[54*640];

// ---------------- PTX helpers ----------------------------------------------
__device__ __forceinline__ uint32_t smem_u32(const void* p) {
    uint32_t a;
    asm("{ .reg .u64 t; cvta.to.shared.u64 t, %1; cvt.u32.u64 %0, t; }"
        : "=r"(a) : "l"(p));
    return a;
}
__device__ __forceinline__ void ldmat4(uint32_t& r0, uint32_t& r1, uint32_t& r2,
                                       uint32_t& r3, uint32_t a) {
    asm volatile("ldmatrix.sync.aligned.m8n8.x4.shared.b16 {%0,%1,%2,%3}, [%4];"
                 : "=r"(r0), "=r"(r1), "=r"(r2), "=r"(r3) : "r"(a));
}
__device__ __forceinline__ void ldmat2t(uint32_t& r0, uint32_t& r1, uint32_t a) {
    asm volatile("ldmatrix.sync.aligned.m8n8.x2.trans.shared.b16 {%0,%1}, [%2];"
                 : "=r"(r0), "=r"(r1) : "r"(a));
}
__device__ __forceinline__ void mma16816(float* c, const uint32_t* a,
                                         const uint32_t* b) {
    asm volatile(
        "mma.sync.aligned.m16n8k16.row.col.f32.f16.f16.f32 "
        "{%0,%1,%2,%3}, {%4,%5,%6,%7}, {%8,%9}, {%0,%1,%2,%3};"
        : "+f"(c[0]), "+f"(c[1]), "+f"(c[2]), "+f"(c[3])
        : "r"(a[0]), "r"(a[1]), "r"(a[2]), "r"(a[3]), "r"(b[0]), "r"(b[1]));
}
__device__ __forceinline__ void cpasync16(uint32_t dst, const void* src, int sz) {
    asm volatile("cp.async.ca.shared.global [%0], [%1], 16, %2;"
                 :: "r"(dst), "l"(src), "r"(sz) : "memory");
}
__device__ __forceinline__ void cp_commit() {
    asm volatile("cp.async.commit_group;" ::: "memory");
}
__device__ __forceinline__ void cp_wait1() {
    asm volatile("cp.async.wait_group 1;" ::: "memory");
}
__device__ __forceinline__ void cp_wait0() {
    asm volatile("cp.async.wait_group 0;" ::: "memory");
}

__device__ __forceinline__ void emit_split(__half* ph, __half* pl,
                                           float x, float y) {
    __half2 h, l;
    h.x = __float2half_rn(x);
    h.y = __float2half_rn(y);
    l.x = __float2half_rn(x - __half2float(h.x));
    l.y = __float2half_rn(y - __half2float(h.y));
    *(__half2*)ph = h;
    *(__half2*)pl = l;
}

// ---------------- prep kernels ---------------------------------------------
__global__ __launch_bounds__(256) void pack_k(const float* __restrict__ x0,
                                              const float* __restrict__ x1) {
    __shared__ float tile[64][65];
    const int s = blockIdx.x;
    const int hw0 = blockIdx.y * 64;
    const int dst = blockIdx.z;
    const int b = s / LL, l = s % LL;
    const float* x = dst ? x1 : x0;
    __half* oh = dst ? g_hmm : g_hin;
    __half* ol = dst ? g_lmm : g_lin;
#pragma unroll
    for (int i = 0; i < 16; i++) {
        int idx = threadIdx.x + i * 256;
        int ci = idx >> 6, hw = idx & 63;
        tile[ci][hw] = x[(((size_t)b * CIN + ci) * LL + l) * HW + hw0 + hw];
    }
    __syncthreads();
#pragma unroll
    for (int i = 0; i < 16; i++) {
        int idx = threadIdx.x + i * 256;
        int hw = idx >> 6, ci = idx & 63;
        float v = tile[ci][hw];
        __half h = __float2half_rn(v);
        size_t o = ((size_t)s * HW + hw0 + hw) * CIN + ci;
        oh[o] = h;
        ol[o] = __float2half_rn(v - __half2float(h));
    }
}

__global__ __launch_bounds__(256) void wprep_k(const float* __restrict__ wq,
                                               const float* __restrict__ wk,
                                               const float* __restrict__ wv) {
    int i = blockIdx.x * 256 + threadIdx.x;
    if (i >= 368640) return;
    const float* w;
    __half *oh, *ol;
    int ntap;
    if (i < 18 * 4096)       { w = wq; oh = (__half*)g_wqh; ol = (__half*)g_wql;
                               ntap = 9; }
    else if (i < 36 * 4096)  { w = wk; oh = (__half*)g_wkh; ol = (__half*)g_wkl;
                               ntap = 9; i -= 18 * 4096; }
    else                     { w = wv; oh = (__half*)g_wvh; ol = (__half*)g_wvl;
                               ntap = 27; i -= 36 * 4096; }
    int sc = i >> 12, r = i & 4095, co = r >> 5, ci32 = r & 31;
    int tap = sc >> 1, chalf = sc & 1;
    int ci = chalf * 32 + ci32;
    float v = w[(co * 64 + ci) * ntap + tap];
    __half h = __float2half_rn(v);
    __half lo = __float2half_rn(v - __half2float(h));
    oh[(size_t)sc * 5120 + co * 40 + ci32] = h;
    ol[(size_t)sc * 5120 + co * 40 + ci32] = lo;
}

// ------ HMMA implicit-GEMM conv, 128co x 128px, 64x64 warp tiles -----------
// 128 threads (4 warps), 2 CTAs/SM. 32-ci sub-chunks, pitch-80B rows.
#define SMEMSZ3 81920   // 2-stage x 40960
#define SMEMSZ1 61440   // 3-stage x 20480

template<int NPASS, int ST>
__device__ __forceinline__ void issue_chunk(
    int sc, int is3d, int p0, int b, int l, uint32_t sb,
    const uint4* wh, const uint4* wl,
    const __half* xh, const __half* xl, int tid) {
    constexpr uint32_t BUF  = (NPASS == 3) ? 40960u : 20480u;
    constexpr uint32_t BOFF = (NPASS == 3) ? 20480u : 10240u;
    const int tap = sc >> 1, chalf = sc & 1;
    int kd, kh, kw;
    if (is3d) { kd = tap / 9; int r = tap % 9; kh = r / 3; kw = r % 3; }
    else      { kd = 0; kh = tap / 3; kw = tap % 3; }
    const uint32_t base = sb + (uint32_t)(sc % ST) * BUF;
    // A: weights (640 uint4 per plane) over 128 threads
#pragma unroll
    for (int i = 0; i < ((NPASS == 3) ? 10 : 5); i++) {
        int idx = tid + i * 128;
        if (idx < ((NPASS == 3) ? 1280 : 640)) {
            int hf = idx >= 640;
            int r = idx - hf * 640;
            const uint4* s = (hf ? wl : wh) + (size_t)sc * 640 + r;
            cpasync16(base + hf * 10240 + r * 16, s, 16);
        }
    }
    // B: input rows, 64B (32 ci), row = tid; 3-pass does both planes
    {
        int row = tid;
        int pg = p0 + row;
        int ih = (pg >> 5) + kh - 1, iw = (pg & 31) + kw - 1;
        int ok = ((unsigned)ih < 32u) && ((unsigned)iw < 32u);
        int ihc = ok ? ih : 0, iwc = ok ? iw : 0;
        size_t soff = ((size_t)((b * LL + l + kd) * HW) + ihc * 32 + iwc) * CIN +
                      chalf * 32;
        int sz = ok ? 16 : 0;
        const __half* s0 = xh + soff;
        uint32_t d0 = base + BOFF + row * 80;
#pragma unroll
        for (int j = 0; j < 4; j++)
            cpasync16(d0 + j * 16, (const char*)s0 + j * 16, sz);
        if (NPASS == 3) {
            const __half* s1 = xl + soff;
            uint32_t d1 = d0 + 10240;
#pragma unroll
            for (int j = 0; j < 4; j++)
                cpasync16(d1 + j * 16, (const char*)s1 + j * 16, sz);
        }
    }
    cp_commit();
}

template<int NPASS, int ST>
__global__ __launch_bounds__(128, 2)
void convmma_k(const float* __restrict__ bias, int mode, int DOUT, int NC,
               int is3d, float scale) {
    extern __shared__ char smem[];
    constexpr uint32_t BUF  = (NPASS == 3) ? 40960u : 20480u;
    constexpr uint32_t BOFF = (NPASS == 3) ? 20480u : 10240u;
    const uint32_t sb = smem_u32(smem);
    const int tid = threadIdx.x, wid = tid >> 5, lane = tid & 31;
    const int p0 = blockIdx.x * 128;
    const int b = blockIdx.y / DOUT, l = blockIdx.y % DOUT;

    const __half *xh, *xl;
    const uint4 *wh, *wl;
    __half *oph, *opl;
    if (mode == 0)      { xh = g_hin; xl = g_lin; wh = g_wqh; wl = g_wql;
                          oph = g_Qh; opl = g_Ql; }
    else if (mode == 1) { xh = g_hmm; xl = g_lmm; wh = g_wkh; wl = g_wkl;
                          oph = g_Kh; opl = g_Kl; }
    else                { xh = g_hmm; xl = g_lmm; wh = g_wvh; wl = g_wvl;
                          oph = g_Vh; opl = g_Vh; }

    const int co0 = (wid & 1) * 64;     // 2 warp rows over 128 co
    const int p0l = (wid >> 1) * 64;    // 2 warp cols over 128 px
    const int bnt = (lane >> 4) & 1;
    const int bkh = (lane >> 3) & 1;

    float acc[4][8][4];
#pragma unroll
    for (int mt = 0; mt < 4; mt++)
#pragma unroll
        for (int nt = 0; nt < 8; nt++)
#pragma unroll
            for (int i = 0; i < 4; i++) acc[mt][nt][i] = 0.f;

    issue_chunk<NPASS, ST>(0, is3d, p0, b, l, sb, wh, wl, xh, xl, tid);
    issue_chunk<NPASS, ST>(1, is3d, p0, b, l, sb, wh, wl, xh, xl, tid);

    for (int sc = 0; sc < NC; sc++) {
        if (sc + 1 < NC) cp_wait1(); else cp_wait0();
        __syncthreads();
        const uint32_t base = sb + (uint32_t)(sc % ST) * BUF;
        const uint32_t aAh = base, aAl = base + 10240;
        const uint32_t aBh = base + BOFF, aBl = base + BOFF + 10240;
#pragma unroll
        for (int k = 0; k < 2; k++) {
            uint32_t bh[8][2], bl[8][2];
#pragma unroll
            for (int pr = 0; pr < 4; pr++) {
                uint32_t off = (uint32_t)(((p0l + (pr * 2 + bnt) * 8 + (lane & 7)) * 40 +
                                           k * 16 + bkh * 8) * 2);
                ldmat4(bh[pr * 2][0], bh[pr * 2][1],
                       bh[pr * 2 + 1][0], bh[pr * 2 + 1][1], aBh + off);
                if (NPASS >= 2)
                    ldmat4(bl[pr * 2][0], bl[pr * 2][1],
                           bl[pr * 2 + 1][0], bl[pr * 2 + 1][1], aBl + off);
            }
            uint32_t a[4][4];
#pragma unroll
            for (int mt = 0; mt < 4; mt++) {
                uint32_t off = (uint32_t)(((co0 + mt * 16 + (lane & 15)) * 40 +
                                           k * 16 + (lane >> 4) * 8) * 2);
                ldmat4(a[mt][0], a[mt][1], a[mt][2], a[mt][3], aAh + off);
            }
#pragma unroll
            for (int mt = 0; mt < 4; mt++)
#pragma unroll
                for (int nt = 0; nt < 8; nt++)
                    mma16816(acc[mt][nt], a[mt], bh[nt]);
            if (NPASS >= 2) {
#pragma unroll
                for (int mt = 0; mt < 4; mt++)
#pragma unroll
                    for (int nt = 0; nt < 8; nt++)
                        mma16816(acc[mt][nt], a[mt], bl[nt]);
            }
            if (NPASS == 3) {
#pragma unroll
                for (int mt = 0; mt < 4; mt++) {
                    uint32_t off = (uint32_t)(((co0 + mt * 16 + (lane & 15)) * 40 +
                                               k * 16 + (lane >> 4) * 8) * 2);
                    ldmat4(a[mt][0], a[mt][1], a[mt][2], a[mt][3], aAl + off);
                }
#pragma unroll
                for (int mt = 0; mt < 4; mt++)
#pragma unroll
                    for (int nt = 0; nt < 8; nt++)
                        mma16816(acc[mt][nt], a[mt], bh[nt]);
            }
        }
        if (ST == 2) __syncthreads();   // buffer sc%2 overwritten by sc+2
        if (sc + 2 < NC)
            issue_chunk<NPASS, ST>(sc + 2, is3d, p0, b, l, sb, wh, wl, xh, xl, tid);
    }

    // epilogue: warp writes 64co x 64px
#pragma unroll
    for (int mt = 0; mt < 4; mt++) {
        int co = co0 + mt * 16 + (lane >> 2);
        float bv0 = bias[co];
        float bv1 = bias[co + 8];
        size_t o0 = ((size_t)(b * CO + co) * DOUT + l) * HW + p0 + p0l;
        size_t o1 = o0 + (size_t)8 * DOUT * HW;
#pragma unroll
        for (int nt = 0; nt < 8; nt++) {
            int p = nt * 8 + (lane & 3) * 2;
            if (NPASS == 1) {
                __half2 v0, v1;
                v0.x = __float2half_rn((acc[mt][nt][0] + bv0) * scale);
                v0.y = __float2half_rn((acc[mt][nt][1] + bv0) * scale);
                v1.x = __float2half_rn((acc[mt][nt][2] + bv1) * scale);
                v1.y = __float2half_rn((acc[mt][nt][3] + bv1) * scale);
                *(__half2*)(oph + o0 + p) = v0;
                *(__half2*)(oph + o1 + p) = v1;
            } else {
                emit_split(oph + o0 + p, opl + o0 + p,
                           (acc[mt][nt][0] + bv0) * scale,
                           (acc[mt][nt][1] + bv0) * scale);
                emit_split(oph + o1 + p, opl + o1 + p,
                           (acc[mt][nt][2] + bv1) * scale,
                           (acc[mt][nt][3] + bv1) * scale);
            }
        }
    }
}

// ---------------- logits: Q.K^T via HMMA, split-K over 9 l-slices ----------
#define LAB  18432
#define LBUF 73728
#define LSMEMSZ (2*LBUF)

__global__ __launch_bounds__(256, 1) void logits2_k() {
    extern __shared__ char smem[];
    const uint32_t sb = smem_u32(smem);
    const int tid = threadIdx.x, wid = tid >> 5, lane = tid & 31;
    const int lc = blockIdx.x, bn = blockIdx.y;
    const int b = bn >> 1, n = bn & 1;
    const int l = n * 9 + lc;

    const __half* srcs[4];
    srcs[0] = g_Qh + ((size_t)(b * CO) * LL + l) * HW;
    srcs[1] = g_Ql + ((size_t)(b * CO) * LL + l) * HW;
    srcs[2] = g_Kh + ((size_t)(b * CO) * LL + l) * HW;
    srcs[3] = g_Kl + ((size_t)(b * CO) * LL + l) * HW;

    const int co0 = (wid & 1) * 64;
    const int p0l = (wid >> 1) * 32;
    const int bnt = (lane >> 4) & 1;
    const int bkh = (lane >> 3) & 1;

    float acc[4][4][4];
#pragma unroll
    for (int mt = 0; mt < 4; mt++)
#pragma unroll
        for (int nt = 0; nt < 4; nt++)
#pragma unroll
            for (int i = 0; i < 4; i++) acc[mt][nt][i] = 0.f;

    auto issue = [&](int ch) {
        const uint32_t base = sb + (ch & 1) * LBUF;
        const int hw0 = ch * 64;
#pragma unroll
        for (int r = tid; r < 512; r += 256) {
            int plane = r >> 7, c = r & 127;
            const __half* s = srcs[plane] + (size_t)c * (LL * HW) + hw0;
            uint32_t dst = base + plane * LAB + c * 144;
#pragma unroll
            for (int j = 0; j < 8; j++)
                cpasync16(dst + j * 16, (const char*)s + j * 16, 16);
        }
        cp_commit();
    };

    issue(0);
    for (int ch = 0; ch < 16; ch++) {
        if (ch + 1 < 16) { issue(ch + 1); cp_wait1(); }
        else             { cp_wait0(); }
        __syncthreads();
        const uint32_t base = sb + (ch & 1) * LBUF;
        const uint32_t aAh = base, aAl = base + LAB;
        const uint32_t aBh = base + 2 * LAB, aBl = base + 3 * LAB;
#pragma unroll
        for (int k = 0; k < 4; k++) {
            uint32_t bh[4][2], bl[4][2];
#pragma unroll
            for (int pr = 0; pr < 2; pr++) {
                uint32_t off = (uint32_t)(((p0l + (pr * 2 + bnt) * 8 + (lane & 7)) * 72 +
                                           k * 16 + bkh * 8) * 2);
                ldmat4(bh[pr * 2][0], bh[pr * 2][1],
                       bh[pr * 2 + 1][0], bh[pr * 2 + 1][1], aBh + off);
                ldmat4(bl[pr * 2][0], bl[pr * 2][1],
                       bl[pr * 2 + 1][0], bl[pr * 2 + 1][1], aBl + off);
            }
            uint32_t a[4][4];
#pragma unroll
            for (int mt = 0; mt < 4; mt++) {
                uint32_t off = (uint32_t)(((co0 + mt * 16 + (lane & 15)) * 72 +
                                           k * 16 + (lane >> 4) * 8) * 2);
                ldmat4(a[mt][0], a[mt][1], a[mt][2], a[mt][3], aAh + off);
            }
#pragma unroll
            for (int mt = 0; mt < 4; mt++)
#pragma unroll
                for (int nt = 0; nt < 4; nt++)
                    mma16816(acc[mt][nt], a[mt], bh[nt]);
#pragma unroll
            for (int mt = 0; mt < 4; mt++)
#pragma unroll
                for (int nt = 0; nt < 4; nt++)
                    mma16816(acc[mt][nt], a[mt], bl[nt]);
#pragma unroll
            for (int mt = 0; mt < 4; mt++) {
                uint32_t off = (uint32_t)(((co0 + mt * 16 + (lane & 15)) * 72 +
                                           k * 16 + (lane >> 4) * 8) * 2);
                ldmat4(a[mt][0], a[mt][1], a[mt][2], a[mt][3], aAl + off);
            }
#pragma unroll
            for (int mt = 0; mt < 4; mt++)
#pragma unroll
                for (int nt = 0; nt < 4; nt++)
                    mma16816(acc[mt][nt], a[mt], bh[nt]);
        }
        __syncthreads();
    }

    float* lp = g_lp + ((size_t)lc * 16 + bn) * CO * CO;
#pragma unroll
    for (int mt = 0; mt < 4; mt++) {
        int c = co0 + mt * 16 + (lane >> 2);
#pragma unroll
        for (int nt = 0; nt < 4; nt++) {
            int m = p0l + nt * 8 + (lane & 3) * 2;
            *(float2*)(lp + (size_t)c * CO + m) =
                make_float2(acc[mt][nt][0], acc[mt][nt][1]);
            *(float2*)(lp + (size_t)(c + 8) * CO + m) =
                make_float2(acc[mt][nt][2], acc[mt][nt][3]);
        }
    }
}

// ---------------- softmax ---------------------------------------------------
__global__ __launch_bounds__(256) void softmax_k() {
    const int warp = (blockIdx.x * 256 + threadIdx.x) >> 5;
    const int lane = threadIdx.x & 31;
    if (warp >= 16 * CO) return;
    const int bn = warp >> 7, c = warp & 127;
    float v[4];
#pragma unroll
    for (int j = 0; j < 4; j++) {
        int m = lane + j * 32;
        float s = 0.f;
#pragma unroll
        for (int p = 0; p < 9; p++)
            s += g_lp[(((size_t)p * 16 + bn) * CO + c) * CO + m];
        v[j] = s;
    }
    float mx = fmaxf(fmaxf(v[0], v[1]), fmaxf(v[2], v[3]));
#pragma unroll
    for (int o = 16; o; o >>= 1) mx = fmaxf(mx, __shfl_xor_sync(0xffffffffu, mx, o));
    float sum = 0.f;
#pragma unroll
    for (int j = 0; j < 4; j++) { v[j] = __expf(v[j] - mx); sum += v[j]; }
#pragma unroll
    for (int o = 16; o; o >>= 1) sum += __shfl_xor_sync(0xffffffffu, sum, o);
    float inv = 1.f / sum;
#pragma unroll
    for (int j = 0; j < 4; j++) {
        float a = v[j] * inv;
        __half h = __float2half_rn(a);
        size_t o = ((size_t)bn * CO + c) * CO + lane + j * 32;
        g_aH[o] = h;
        g_aL[o] = __float2half_rn(a - __half2float(h));
    }
}

// ---------------- out: attn(hi,lo) x V(fp16) via HMMA, 2 passes ------------
#define OPITCH 272
#define OTILE  34816
#define OSMEM  (3*OTILE)

__global__ __launch_bounds__(256, 1) void out2_k(float* __restrict__ out) {
    extern __shared__ char smem[];
    const uint32_t sb = smem_u32(smem);
    const int tid = threadIdx.x, wid = tid >> 5, lane = tid & 31;
    const int pt = blockIdx.x, b = blockIdx.y;
    const int l = pt >> 3;
    const int hw0 = (pt & 7) * 128;
    const int bn = b * 2 + (l >> 3);

    {
        int c = tid & 127;
        if (tid < 128) {
            const __half* s = g_aH + ((size_t)bn * CO + c) * CO;
            uint32_t dst = sb + c * OPITCH;
#pragma unroll
            for (int j = 0; j < 16; j++)
                cpasync16(dst + j * 16, (const char*)s + j * 16, 16);
            const __half* sv = g_Vh + ((size_t)(b * CO + c) * LV + l) * HW + hw0;
            uint32_t dv = sb + 2 * OTILE + c * OPITCH;
#pragma unroll
            for (int j = 0; j < 16; j++)
                cpasync16(dv + j * 16, (const char*)sv + j * 16, 16);
        } else {
            const __half* s = g_aL + ((size_t)bn * CO + c) * CO;
            uint32_t dst = sb + OTILE + c * OPITCH;
#pragma unroll
            for (int j = 0; j < 16; j++)
                cpasync16(dst + j * 16, (const char*)s + j * 16, 16);
        }
    }
    cp_commit();
    cp_wait0();
    __syncthreads();

    const int co0 = (wid & 1) * 64;
    const int p0l = (wid >> 1) * 32;
    const uint32_t aAh = sb, aAl = sb + OTILE;
    const uint32_t aB = sb + 2 * OTILE;

    float acc[4][4][4];
#pragma unroll
    for (int mt = 0; mt < 4; mt++)
#pragma unroll
        for (int nt = 0; nt < 4; nt++)
#pragma unroll
            for (int i = 0; i < 4; i++) acc[mt][nt][i] = 0.f;

#pragma unroll
    for (int kc = 0; kc < 8; kc++) {
        uint32_t bh[4][2];
#pragma unroll
        for (int nt = 0; nt < 4; nt++) {
            uint32_t off = (uint32_t)((kc * 16 + (lane & 15)) * OPITCH +
                                      (p0l + nt * 8) * 2);
            ldmat2t(bh[nt][0], bh[nt][1], aB + off);
        }
        uint32_t a[4][4];
#pragma unroll
        for (int mt = 0; mt < 4; mt++) {
            uint32_t off = (uint32_t)((co0 + mt * 16 + (lane & 15)) * OPITCH +
                                      kc * 32 + (lane >> 4) * 16);
            ldmat4(a[mt][0], a[mt][1], a[mt][2], a[mt][3], aAh + off);
        }
#pragma unroll
        for (int mt = 0; mt < 4; mt++)
#pragma unroll
            for (int nt = 0; nt < 4; nt++)
                mma16816(acc[mt][nt], a[mt], bh[nt]);
#pragma unroll
        for (int mt = 0; mt < 4; mt++) {
            uint32_t off = (uint32_t)((co0 + mt * 16 + (lane & 15)) * OPITCH +
                                      kc * 32 + (lane >> 4) * 16);
            ldmat4(a[mt][0], a[mt][1], a[mt][2], a[mt][3], aAl + off);
        }
#pragma unroll
        for (int mt = 0; mt < 4; mt++)
#pragma unroll
            for (int nt = 0; nt < 4; nt++)
                mma16816(acc[mt][nt], a[mt], bh[nt]);
    }

#pragma unroll
    for (int mt = 0; mt < 4; mt++) {
        int c = co0 + mt * 16 + (lane >> 2);
        float* o0 = out + ((size_t)(b * CO + c) * LV + l) * HW + hw0 + p0l;
        float* o1 = o0 + (size_t)8 * LV * HW;
#pragma unroll
        for (int nt = 0; nt < 4; nt++) {
            int p = nt * 8 + (lane & 3) * 2;
            *(float2*)(o0 + p) = make_float2(acc[mt][nt][0], acc[mt][nt][1]);
            *(float2*)(o1 + p) = make_float2(acc[mt][nt][2], acc[mt][nt][3]);
        }
    }
}

// ---------------------------------------------------------------------------
extern "C" void kernel_launch(void* const* d_in, const int* in_sizes, int n_in,
                              void* d_out, int out_size) {
    const float* input  = (const float*)d_in[0];
    const float* memory = (const float*)d_in[1];
    const float* wq = (const float*)d_in[2];
    const float* bq = (const float*)d_in[3];
    const float* wk = (const float*)d_in[4];
    const float* bk = (const float*)d_in[5];
    const float* wv = (const float*)d_in[6];
    const float* bv = (const float*)d_in[7];
    float* out = (float*)d_out;

    cudaFuncSetAttribute((const void*)convmma_k<3, 2>,
                         cudaFuncAttributeMaxDynamicSharedMemorySize, SMEMSZ3);
    cudaFuncSetAttribute((const void*)convmma_k<1, 3>,
                         cudaFuncAttributeMaxDynamicSharedMemorySize, SMEMSZ1);
    cudaFuncSetAttribute((const void*)logits2_k,
                         cudaFuncAttributeMaxDynamicSharedMemorySize, LSMEMSZ);
    cudaFuncSetAttribute((const void*)out2_k,
                         cudaFuncAttributeMaxDynamicSharedMemorySize, OSMEM);

    pack_k<<<dim3(BB * LL, 16, 2), 256>>>(input, memory);
    wprep_k<<<(368640 + 255) / 256, 256>>>(wq, wk, wv);

    convmma_k<3, 2><<<dim3(8, BB * LL), 128, SMEMSZ3>>>(bq, 0, LL, 18, 0, 0.5f);
    convmma_k<3, 2><<<dim3(8, BB * LL), 128, SMEMSZ3>>>(bk, 1, LL, 18, 0, 1.0f);
    convmma_k<1, 3><<<dim3(8, BB * LV), 128, SMEMSZ1>>>(bv, 2, LV, 54, 1, 1.0f);

    logits2_k<<<dim3(9, 16), 256, LSMEMSZ>>>();
    softmax_k<<<256, 256>>>();
    out2_k<<<dim3(128, 8), 256, OSMEM>>>(out);
}

// round 13
// speedup vs baseline: 1.0519x; 1.0519x over previous
#include <cuda_runtime.h>
#include <cuda_fp16.h>
#include <cstdint>

#define BB   8
#define CIN  64
#define CO   128
#define LL   18
#define LV   16
#define HW   1024
#define NH   2

// ---------------- scratch (device globals; no allocation allowed) ----------
__device__ float g_lp[(size_t)9*BB*NH*CO*CO];

__device__ __half g_Qh[(size_t)BB*CO*LL*HW];
__device__ __half g_Ql[(size_t)BB*CO*LL*HW];
__device__ __half g_Kh[(size_t)BB*CO*LL*HW];
__device__ __half g_Kl[(size_t)BB*CO*LL*HW];
__device__ __half g_Vh[(size_t)BB*CO*LV*HW];
__device__ __half g_aH[(size_t)BB*NH*CO*CO];
__device__ __half g_aL[(size_t)BB*NH*CO*CO];

__device__ __half g_hin[(size_t)BB*LL*HW*CIN];
__device__ __half g_lin[(size_t)BB*LL*HW*CIN];
__device__ __half g_hmm[(size_t)BB*LL*HW*CIN];
__device__ __half g_lmm[(size_t)BB*LL*HW*CIN];

// weight images, 32-ci sub-chunks, pitch 40 halves: [sc][co=128][40]
__device__ uint4 g_wqh[18*640], g_wql[18*640];
__device__ uint4 g_wkh[18*640], g_wkl[18*640];
__device__ uint4 g_wvh[54*640], g_wvl[54*640];

// ---------------- PTX helpers ----------------------------------------------
__device__ __forceinline__ uint32_t smem_u32(const void* p) {
    uint32_t a;
    asm("{ .reg .u64 t; cvta.to.shared.u64 t, %1; cvt.u32.u64 %0, t; }"
        : "=r"(a) : "l"(p));
    return a;
}
__device__ __forceinline__ void ldmat4(uint32_t& r0, uint32_t& r1, uint32_t& r2,
                                       uint32_t& r3, uint32_t a) {
    asm volatile("ldmatrix.sync.aligned.m8n8.x4.shared.b16 {%0,%1,%2,%3}, [%4];"
                 : "=r"(r0), "=r"(r1), "=r"(r2), "=r"(r3) : "r"(a));
}
__device__ __forceinline__ void ldmat2t(uint32_t& r0, uint32_t& r1, uint32_t a) {
    asm volatile("ldmatrix.sync.aligned.m8n8.x2.trans.shared.b16 {%0,%1}, [%2];"
                 : "=r"(r0), "=r"(r1) : "r"(a));
}
__device__ __forceinline__ void mma16816(float* c, const uint32_t* a,
                                         const uint32_t* b) {
    asm volatile(
        "mma.sync.aligned.m16n8k16.row.col.f32.f16.f16.f32 "
        "{%0,%1,%2,%3}, {%4,%5,%6,%7}, {%8,%9}, {%0,%1,%2,%3};"
        : "+f"(c[0]), "+f"(c[1]), "+f"(c[2]), "+f"(c[3])
        : "r"(a[0]), "r"(a[1]), "r"(a[2]), "r"(a[3]), "r"(b[0]), "r"(b[1]));
}
__device__ __forceinline__ void cpasync16(uint32_t dst, const void* src, int sz) {
    asm volatile("cp.async.ca.shared.global [%0], [%1], 16, %2;"
                 :: "r"(dst), "l"(src), "r"(sz) : "memory");
}
__device__ __forceinline__ void cp_commit() {
    asm volatile("cp.async.commit_group;" ::: "memory");
}
__device__ __forceinline__ void cp_wait1() {
    asm volatile("cp.async.wait_group 1;" ::: "memory");
}
__device__ __forceinline__ void cp_wait0() {
    asm volatile("cp.async.wait_group 0;" ::: "memory");
}

__device__ __forceinline__ void emit_split(__half* ph, __half* pl,
                                           float x, float y) {
    __half2 h, l;
    h.x = __float2half_rn(x);
    h.y = __float2half_rn(y);
    l.x = __float2half_rn(x - __half2float(h.x));
    l.y = __float2half_rn(y - __half2float(h.y));
    *(__half2*)ph = h;
    *(__half2*)pl = l;
}

// ---------------- prep kernels ---------------------------------------------
__global__ __launch_bounds__(256) void pack_k(const float* __restrict__ x0,
                                              const float* __restrict__ x1) {
    __shared__ float tile[64][65];
    const int s = blockIdx.x;
    const int hw0 = blockIdx.y * 64;
    const int dst = blockIdx.z;
    const int b = s / LL, l = s % LL;
    const float* x = dst ? x1 : x0;
    __half* oh = dst ? g_hmm : g_hin;
    __half* ol = dst ? g_lmm : g_lin;
#pragma unroll
    for (int i = 0; i < 16; i++) {
        int idx = threadIdx.x + i * 256;
        int ci = idx >> 6, hw = idx & 63;
        tile[ci][hw] = x[(((size_t)b * CIN + ci) * LL + l) * HW + hw0 + hw];
    }
    __syncthreads();
#pragma unroll
    for (int i = 0; i < 16; i++) {
        int idx = threadIdx.x + i * 256;
        int hw = idx >> 6, ci = idx & 63;
        float v = tile[ci][hw];
        __half h = __float2half_rn(v);
        size_t o = ((size_t)s * HW + hw0 + hw) * CIN + ci;
        oh[o] = h;
        ol[o] = __float2half_rn(v - __half2float(h));
    }
}

__global__ __launch_bounds__(256) void wprep_k(const float* __restrict__ wq,
                                               const float* __restrict__ wk,
                                               const float* __restrict__ wv) {
    int i = blockIdx.x * 256 + threadIdx.x;
    if (i >= 368640) return;
    const float* w;
    __half *oh, *ol;
    int ntap;
    if (i < 18 * 4096)       { w = wq; oh = (__half*)g_wqh; ol = (__half*)g_wql;
                               ntap = 9; }
    else if (i < 36 * 4096)  { w = wk; oh = (__half*)g_wkh; ol = (__half*)g_wkl;
                               ntap = 9; i -= 18 * 4096; }
    else                     { w = wv; oh = (__half*)g_wvh; ol = (__half*)g_wvl;
                               ntap = 27; i -= 36 * 4096; }
    int sc = i >> 12, r = i & 4095, co = r >> 5, ci32 = r & 31;
    int tap = sc >> 1, chalf = sc & 1;
    int ci = chalf * 32 + ci32;
    float v = w[(co * 64 + ci) * ntap + tap];
    __half h = __float2half_rn(v);
    __half lo = __float2half_rn(v - __half2float(h));
    oh[(size_t)sc * 5120 + co * 40 + ci32] = h;
    ol[(size_t)sc * 5120 + co * 40 + ci32] = lo;
}

// ------ Q/K conv: 3-pass, 128 threads, 64x64 warp tiles, 2 CTAs/SM ---------
#define SMEMSZ3 81920   // 2-stage x 40960

__device__ __forceinline__ void issue_qk(
    int sc, int p0, int b, int l, uint32_t sb,
    const uint4* wh, const uint4* wl,
    const __half* xh, const __half* xl, int tid) {
    const int tap = sc >> 1, chalf = sc & 1;
    const int kh = tap / 3, kw = tap % 3;
    const uint32_t base = sb + (uint32_t)(sc & 1) * 40960u;
#pragma unroll
    for (int i = 0; i < 10; i++) {
        int idx = tid + i * 128;
        if (idx < 1280) {
            int hf = idx >= 640;
            int r = idx - hf * 640;
            const uint4* s = (hf ? wl : wh) + (size_t)sc * 640 + r;
            cpasync16(base + hf * 10240 + r * 16, s, 16);
        }
    }
    {
        int row = tid;
        int pg = p0 + row;
        int ih = (pg >> 5) + kh - 1, iw = (pg & 31) + kw - 1;
        int ok = ((unsigned)ih < 32u) && ((unsigned)iw < 32u);
        int ihc = ok ? ih : 0, iwc = ok ? iw : 0;
        size_t soff = ((size_t)((b * LL + l) * HW) + ihc * 32 + iwc) * CIN +
                      chalf * 32;
        int sz = ok ? 16 : 0;
        const __half* s0 = xh + soff;
        uint32_t d0 = base + 20480u + row * 80;
#pragma unroll
        for (int j = 0; j < 4; j++)
            cpasync16(d0 + j * 16, (const char*)s0 + j * 16, sz);
        const __half* s1 = xl + soff;
        uint32_t d1 = d0 + 10240;
#pragma unroll
        for (int j = 0; j < 4; j++)
            cpasync16(d1 + j * 16, (const char*)s1 + j * 16, sz);
    }
    cp_commit();
}

__global__ __launch_bounds__(128, 2)
void convqk_k(const float* __restrict__ bias, int mode, float scale) {
    extern __shared__ char smem[];
    const uint32_t sb = smem_u32(smem);
    const int tid = threadIdx.x, wid = tid >> 5, lane = tid & 31;
    const int p0 = blockIdx.x * 128;
    const int b = blockIdx.y / LL, l = blockIdx.y % LL;

    const __half *xh, *xl;
    const uint4 *wh, *wl;
    __half *oph, *opl;
    if (mode == 0) { xh = g_hin; xl = g_lin; wh = g_wqh; wl = g_wql;
                     oph = g_Qh; opl = g_Ql; }
    else           { xh = g_hmm; xl = g_lmm; wh = g_wkh; wl = g_wkl;
                     oph = g_Kh; opl = g_Kl; }

    const int co0 = (wid & 1) * 64;
    const int p0l = (wid >> 1) * 64;
    const int bnt = (lane >> 4) & 1;
    const int bkh = (lane >> 3) & 1;

    float acc[4][8][4];
#pragma unroll
    for (int mt = 0; mt < 4; mt++)
#pragma unroll
        for (int nt = 0; nt < 8; nt++)
#pragma unroll
            for (int i = 0; i < 4; i++) acc[mt][nt][i] = 0.f;

    issue_qk(0, p0, b, l, sb, wh, wl, xh, xl, tid);
    issue_qk(1, p0, b, l, sb, wh, wl, xh, xl, tid);

    for (int sc = 0; sc < 18; sc++) {
        if (sc + 1 < 18) cp_wait1(); else cp_wait0();
        __syncthreads();
        const uint32_t base = sb + (uint32_t)(sc & 1) * 40960u;
        const uint32_t aAh = base, aAl = base + 10240;
        const uint32_t aBh = base + 20480u, aBl = base + 30720u;
#pragma unroll
        for (int k = 0; k < 2; k++) {
            uint32_t bh[8][2], bl[8][2];
#pragma unroll
            for (int pr = 0; pr < 4; pr++) {
                uint32_t off = (uint32_t)(((p0l + (pr * 2 + bnt) * 8 + (lane & 7)) * 40 +
                                           k * 16 + bkh * 8) * 2);
                ldmat4(bh[pr * 2][0], bh[pr * 2][1],
                       bh[pr * 2 + 1][0], bh[pr * 2 + 1][1], aBh + off);
                ldmat4(bl[pr * 2][0], bl[pr * 2][1],
                       bl[pr * 2 + 1][0], bl[pr * 2 + 1][1], aBl + off);
            }
            uint32_t a[4][4];
#pragma unroll
            for (int mt = 0; mt < 4; mt++) {
                uint32_t off = (uint32_t)(((co0 + mt * 16 + (lane & 15)) * 40 +
                                           k * 16 + (lane >> 4) * 8) * 2);
                ldmat4(a[mt][0], a[mt][1], a[mt][2], a[mt][3], aAh + off);
            }
#pragma unroll
            for (int mt = 0; mt < 4; mt++)
#pragma unroll
                for (int nt = 0; nt < 8; nt++)
                    mma16816(acc[mt][nt], a[mt], bh[nt]);
#pragma unroll
            for (int mt = 0; mt < 4; mt++)
#pragma unroll
                for (int nt = 0; nt < 8; nt++)
                    mma16816(acc[mt][nt], a[mt], bl[nt]);
#pragma unroll
            for (int mt = 0; mt < 4; mt++) {
                uint32_t off = (uint32_t)(((co0 + mt * 16 + (lane & 15)) * 40 +
                                           k * 16 + (lane >> 4) * 8) * 2);
                ldmat4(a[mt][0], a[mt][1], a[mt][2], a[mt][3], aAl + off);
            }
#pragma unroll
            for (int mt = 0; mt < 4; mt++)
#pragma unroll
                for (int nt = 0; nt < 8; nt++)
                    mma16816(acc[mt][nt], a[mt], bh[nt]);
        }
        __syncthreads();
        if (sc + 2 < 18)
            issue_qk(sc + 2, p0, b, l, sb, wh, wl, xh, xl, tid);
    }

#pragma unroll
    for (int mt = 0; mt < 4; mt++) {
        int co = co0 + mt * 16 + (lane >> 2);
        float bv0 = bias[co];
        float bv1 = bias[co + 8];
        size_t o0 = ((size_t)(b * CO + co) * LL + l) * HW + p0 + p0l;
        size_t o1 = o0 + (size_t)8 * LL * HW;
#pragma unroll
        for (int nt = 0; nt < 8; nt++) {
            int p = nt * 8 + (lane & 3) * 2;
            emit_split(oph + o0 + p, opl + o0 + p,
                       (acc[mt][nt][0] + bv0) * scale,
                       (acc[mt][nt][1] + bv0) * scale);
            emit_split(oph + o1 + p, opl + o1 + p,
                       (acc[mt][nt][2] + bv1) * scale,
                       (acc[mt][nt][3] + bv1) * scale);
        }
    }
}

// ------ V conv: 1-pass, 256 threads, 64x32 warp tiles, 2 CTAs/SM -----------
#define SMEMSZ1 61440   // 3-stage x 20480

__device__ __forceinline__ void issue_v(
    int sc, int p0, int b, int l, uint32_t sb,
    const uint4* wh, const __half* xh, int tid) {
    const int tap = sc >> 1, chalf = sc & 1;
    const int kd = tap / 9;
    const int r9 = tap % 9;
    const int kh = r9 / 3, kw = r9 % 3;
    const uint32_t base = sb + (uint32_t)(sc % 3) * 20480u;
#pragma unroll
    for (int i = 0; i < 3; i++) {
        int idx = tid + i * 256;
        if (idx < 640) {
            const uint4* s = wh + (size_t)sc * 640 + idx;
            cpasync16(base + idx * 16, s, 16);
        }
    }
    {
        int row = tid >> 1;
        int j0 = (tid & 1) * 2;
        int pg = p0 + row;
        int ih = (pg >> 5) + kh - 1, iw = (pg & 31) + kw - 1;
        int ok = ((unsigned)ih < 32u) && ((unsigned)iw < 32u);
        int ihc = ok ? ih : 0, iwc = ok ? iw : 0;
        const __half* s = xh +
            ((size_t)((b * LL + l + kd) * HW) + ihc * 32 + iwc) * CIN + chalf * 32;
        uint32_t dst = base + 10240u + row * 80;
        int sz = ok ? 16 : 0;
#pragma unroll
        for (int j = 0; j < 2; j++)
            cpasync16(dst + (j0 + j) * 16, (const char*)s + (j0 + j) * 16, sz);
    }
    cp_commit();
}

__global__ __launch_bounds__(256, 2)
void convv_k(const float* __restrict__ bias) {
    extern __shared__ char smem[];
    const uint32_t sb = smem_u32(smem);
    const int tid = threadIdx.x, wid = tid >> 5, lane = tid & 31;
    const int p0 = blockIdx.x * 128;
    const int b = blockIdx.y / LV, l = blockIdx.y % LV;

    const int co0 = (wid & 1) * 64;
    const int p0l = (wid >> 1) * 32;
    const int bnt = (lane >> 4) & 1;
    const int bkh = (lane >> 3) & 1;

    float acc[4][4][4];
#pragma unroll
    for (int mt = 0; mt < 4; mt++)
#pragma unroll
        for (int nt = 0; nt < 4; nt++)
#pragma unroll
            for (int i = 0; i < 4; i++) acc[mt][nt][i] = 0.f;

    issue_v(0, p0, b, l, sb, g_wvh, g_hmm, tid);
    issue_v(1, p0, b, l, sb, g_wvh, g_hmm, tid);

    for (int sc = 0; sc < 54; sc++) {
        if (sc + 1 < 54) cp_wait1(); else cp_wait0();
        __syncthreads();
        const uint32_t base = sb + (uint32_t)(sc % 3) * 20480u;
        const uint32_t aAh = base;
        const uint32_t aBh = base + 10240u;
#pragma unroll
        for (int k = 0; k < 2; k++) {
            uint32_t bh[4][2];
#pragma unroll
            for (int pr = 0; pr < 2; pr++) {
                uint32_t off = (uint32_t)(((p0l + (pr * 2 + bnt) * 8 + (lane & 7)) * 40 +
                                           k * 16 + bkh * 8) * 2);
                ldmat4(bh[pr * 2][0], bh[pr * 2][1],
                       bh[pr * 2 + 1][0], bh[pr * 2 + 1][1], aBh + off);
            }
            uint32_t a[4][4];
#pragma unroll
            for (int mt = 0; mt < 4; mt++) {
                uint32_t off = (uint32_t)(((co0 + mt * 16 + (lane & 15)) * 40 +
                                           k * 16 + (lane >> 4) * 8) * 2);
                ldmat4(a[mt][0], a[mt][1], a[mt][2], a[mt][3], aAh + off);
            }
#pragma unroll
            for (int mt = 0; mt < 4; mt++)
#pragma unroll
                for (int nt = 0; nt < 4; nt++)
                    mma16816(acc[mt][nt], a[mt], bh[nt]);
        }
        if (sc + 2 < 54)
            issue_v(sc + 2, p0, b, l, sb, g_wvh, g_hmm, tid);
    }

#pragma unroll
    for (int mt = 0; mt < 4; mt++) {
        int co = co0 + mt * 16 + (lane >> 2);
        float bv0 = bias[co];
        float bv1 = bias[co + 8];
        size_t o0 = ((size_t)(b * CO + co) * LV + l) * HW + p0 + p0l;
        size_t o1 = o0 + (size_t)8 * LV * HW;
#pragma unroll
        for (int nt = 0; nt < 4; nt++) {
            int p = nt * 8 + (lane & 3) * 2;
            __half2 v0, v1;
            v0.x = __float2half_rn(acc[mt][nt][0] + bv0);
            v0.y = __float2half_rn(acc[mt][nt][1] + bv0);
            v1.x = __float2half_rn(acc[mt][nt][2] + bv1);
            v1.y = __float2half_rn(acc[mt][nt][3] + bv1);
            *(__half2*)(g_Vh + o0 + p) = v0;
            *(__half2*)(g_Vh + o1 + p) = v1;
        }
    }
}

// ---------------- logits: Q.K^T via HMMA, split-K over 9 l-slices ----------
#define LAB  18432
#define LBUF 73728
#define LSMEMSZ (2*LBUF)

__global__ __launch_bounds__(256, 1) void logits2_k() {
    extern __shared__ char smem[];
    const uint32_t sb = smem_u32(smem);
    const int tid = threadIdx.x, wid = tid >> 5, lane = tid & 31;
    const int lc = blockIdx.x, bn = blockIdx.y;
    const int b = bn >> 1, n = bn & 1;
    const int l = n * 9 + lc;

    const __half* srcs[4];
    srcs[0] = g_Qh + ((size_t)(b * CO) * LL + l) * HW;
    srcs[1] = g_Ql + ((size_t)(b * CO) * LL + l) * HW;
    srcs[2] = g_Kh + ((size_t)(b * CO) * LL + l) * HW;
    srcs[3] = g_Kl + ((size_t)(b * CO) * LL + l) * HW;

    const int co0 = (wid & 1) * 64;
    const int p0l = (wid >> 1) * 32;
    const int bnt = (lane >> 4) & 1;
    const int bkh = (lane >> 3) & 1;

    float acc[4][4][4];
#pragma unroll
    for (int mt = 0; mt < 4; mt++)
#pragma unroll
        for (int nt = 0; nt < 4; nt++)
#pragma unroll
            for (int i = 0; i < 4; i++) acc[mt][nt][i] = 0.f;

    auto issue = [&](int ch) {
        const uint32_t base = sb + (ch & 1) * LBUF;
        const int hw0 = ch * 64;
#pragma unroll
        for (int r = tid; r < 512; r += 256) {
            int plane = r >> 7, c = r & 127;
            const __half* s = srcs[plane] + (size_t)c * (LL * HW) + hw0;
            uint32_t dst = base + plane * LAB + c * 144;
#pragma unroll
            for (int j = 0; j < 8; j++)
                cpasync16(dst + j * 16, (const char*)s + j * 16, 16);
        }
        cp_commit();
    };

    issue(0);
    for (int ch = 0; ch < 16; ch++) {
        if (ch + 1 < 16) { issue(ch + 1); cp_wait1(); }
        else             { cp_wait0(); }
        __syncthreads();
        const uint32_t base = sb + (ch & 1) * LBUF;
        const uint32_t aAh = base, aAl = base + LAB;
        const uint32_t aBh = base + 2 * LAB, aBl = base + 3 * LAB;
#pragma unroll
        for (int k = 0; k < 4; k++) {
            uint32_t bh[4][2], bl[4][2];
#pragma unroll
            for (int pr = 0; pr < 2; pr++) {
                uint32_t off = (uint32_t)(((p0l + (pr * 2 + bnt) * 8 + (lane & 7)) * 72 +
                                           k * 16 + bkh * 8) * 2);
                ldmat4(bh[pr * 2][0], bh[pr * 2][1],
                       bh[pr * 2 + 1][0], bh[pr * 2 + 1][1], aBh + off);
                ldmat4(bl[pr * 2][0], bl[pr * 2][1],
                       bl[pr * 2 + 1][0], bl[pr * 2 + 1][1], aBl + off);
            }
            uint32_t a[4][4];
#pragma unroll
            for (int mt = 0; mt < 4; mt++) {
                uint32_t off = (uint32_t)(((co0 + mt * 16 + (lane & 15)) * 72 +
                                           k * 16 + (lane >> 4) * 8) * 2);
                ldmat4(a[mt][0], a[mt][1], a[mt][2], a[mt][3], aAh + off);
            }
#pragma unroll
            for (int mt = 0; mt < 4; mt++)
#pragma unroll
                for (int nt = 0; nt < 4; nt++)
                    mma16816(acc[mt][nt], a[mt], bh[nt]);
#pragma unroll
            for (int mt = 0; mt < 4; mt++)
#pragma unroll
                for (int nt = 0; nt < 4; nt++)
                    mma16816(acc[mt][nt], a[mt], bl[nt]);
#pragma unroll
            for (int mt = 0; mt < 4; mt++) {
                uint32_t off = (uint32_t)(((co0 + mt * 16 + (lane & 15)) * 72 +
                                           k * 16 + (lane >> 4) * 8) * 2);
                ldmat4(a[mt][0], a[mt][1], a[mt][2], a[mt][3], aAl + off);
            }
#pragma unroll
            for (int mt = 0; mt < 4; mt++)
#pragma unroll
                for (int nt = 0; nt < 4; nt++)
                    mma16816(acc[mt][nt], a[mt], bh[nt]);
        }
        __syncthreads();
    }

    float* lp = g_lp + ((size_t)lc * 16 + bn) * CO * CO;
#pragma unroll
    for (int mt = 0; mt < 4; mt++) {
        int c = co0 + mt * 16 + (lane >> 2);
#pragma unroll
        for (int nt = 0; nt < 4; nt++) {
            int m = p0l + nt * 8 + (lane & 3) * 2;
            *(float2*)(lp + (size_t)c * CO + m) =
                make_float2(acc[mt][nt][0], acc[mt][nt][1]);
            *(float2*)(lp + (size_t)(c + 8) * CO + m) =
                make_float2(acc[mt][nt][2], acc[mt][nt][3]);
        }
    }
}

// ---------------- softmax ---------------------------------------------------
__global__ __launch_bounds__(256) void softmax_k() {
    const int warp = (blockIdx.x * 256 + threadIdx.x) >> 5;
    const int lane = threadIdx.x & 31;
    if (warp >= 16 * CO) return;
    const int bn = warp >> 7, c = warp & 127;
    float v[4];
#pragma unroll
    for (int j = 0; j < 4; j++) {
        int m = lane + j * 32;
        float s = 0.f;
#pragma unroll
        for (int p = 0; p < 9; p++)
            s += g_lp[(((size_t)p * 16 + bn) * CO + c) * CO + m];
        v[j] = s;
    }
    float mx = fmaxf(fmaxf(v[0], v[1]), fmaxf(v[2], v[3]));
#pragma unroll
    for (int o = 16; o; o >>= 1) mx = fmaxf(mx, __shfl_xor_sync(0xffffffffu, mx, o));
    float sum = 0.f;
#pragma unroll
    for (int j = 0; j < 4; j++) { v[j] = __expf(v[j] - mx); sum += v[j]; }
#pragma unroll
    for (int o = 16; o; o >>= 1) sum += __shfl_xor_sync(0xffffffffu, sum, o);
    float inv = 1.f / sum;
#pragma unroll
    for (int j = 0; j < 4; j++) {
        float a = v[j] * inv;
        __half h = __float2half_rn(a);
        size_t o = ((size_t)bn * CO + c) * CO + lane + j * 32;
        g_aH[o] = h;
        g_aL[o] = __float2half_rn(a - __half2float(h));
    }
}

// ---------------- out: attn(hi,lo) x V(fp16) via HMMA, 2 passes ------------
#define OPITCH 272
#define OTILE  34816
#define OSMEM  (3*OTILE)

__global__ __launch_bounds__(256, 1) void out2_k(float* __restrict__ out) {
    extern __shared__ char smem[];
    const uint32_t sb = smem_u32(smem);
    const int tid = threadIdx.x, wid = tid >> 5, lane = tid & 31;
    const int pt = blockIdx.x, b = blockIdx.y;
    const int l = pt >> 3;
    const int hw0 = (pt & 7) * 128;
    const int bn = b * 2 + (l >> 3);

    {
        int c = tid & 127;
        if (tid < 128) {
            const __half* s = g_aH + ((size_t)bn * CO + c) * CO;
            uint32_t dst = sb + c * OPITCH;
#pragma unroll
            for (int j = 0; j < 16; j++)
                cpasync16(dst + j * 16, (const char*)s + j * 16, 16);
            const __half* sv = g_Vh + ((size_t)(b * CO + c) * LV + l) * HW + hw0;
            uint32_t dv = sb + 2 * OTILE + c * OPITCH;
#pragma unroll
            for (int j = 0; j < 16; j++)
                cpasync16(dv + j * 16, (const char*)sv + j * 16, 16);
        } else {
            const __half* s = g_aL + ((size_t)bn * CO + c) * CO;
            uint32_t dst = sb + OTILE + c * OPITCH;
#pragma unroll
            for (int j = 0; j < 16; j++)
                cpasync16(dst + j * 16, (const char*)s + j * 16, 16);
        }
    }
    cp_commit();
    cp_wait0();
    __syncthreads();

    const int co0 = (wid & 1) * 64;
    const int p0l = (wid >> 1) * 32;
    const uint32_t aAh = sb, aAl = sb + OTILE;
    const uint32_t aB = sb + 2 * OTILE;

    float acc[4][4][4];
#pragma unroll
    for (int mt = 0; mt < 4; mt++)
#pragma unroll
        for (int nt = 0; nt < 4; nt++)
#pragma unroll
            for (int i = 0; i < 4; i++) acc[mt][nt][i] = 0.f;

#pragma unroll
    for (int kc = 0; kc < 8; kc++) {
        uint32_t bh[4][2];
#pragma unroll
        for (int nt = 0; nt < 4; nt++) {
            uint32_t off = (uint32_t)((kc * 16 + (lane & 15)) * OPITCH +
                                      (p0l + nt * 8) * 2);
            ldmat2t(bh[nt][0], bh[nt][1], aB + off);
        }
        uint32_t a[4][4];
#pragma unroll
        for (int mt = 0; mt < 4; mt++) {
            uint32_t off = (uint32_t)((co0 + mt * 16 + (lane & 15)) * OPITCH +
                                      kc * 32 + (lane >> 4) * 16);
            ldmat4(a[mt][0], a[mt][1], a[mt][2], a[mt][3], aAh + off);
        }
#pragma unroll
        for (int mt = 0; mt < 4; mt++)
#pragma unroll
            for (int nt = 0; nt < 4; nt++)
                mma16816(acc[mt][nt], a[mt], bh[nt]);
#pragma unroll
        for (int mt = 0; mt < 4; mt++) {
            uint32_t off = (uint32_t)((co0 + mt * 16 + (lane & 15)) * OPITCH +
                                      kc * 32 + (lane >> 4) * 16);
            ldmat4(a[mt][0], a[mt][1], a[mt][2], a[mt][3], aAl + off);
        }
#pragma unroll
        for (int mt = 0; mt < 4; mt++)
#pragma unroll
            for (int nt = 0; nt < 4; nt++)
                mma16816(acc[mt][nt], a[mt], bh[nt]);
    }

#pragma unroll
    for (int mt = 0; mt < 4; mt++) {
        int c = co0 + mt * 16 + (lane >> 2);
        float* o0 = out + ((size_t)(b * CO + c) * LV + l) * HW + hw0 + p0l;
        float* o1 = o0 + (size_t)8 * LV * HW;
#pragma unroll
        for (int nt = 0; nt < 4; nt++) {
            int p = nt * 8 + (lane & 3) * 2;
            *(float2*)(o0 + p) = make_float2(acc[mt][nt][0], acc[mt][nt][1]);
            *(float2*)(o1 + p) = make_float2(acc[mt][nt][2], acc[mt][nt][3]);
        }
    }
}

// ---------------------------------------------------------------------------
extern "C" void kernel_launch(void* const* d_in, const int* in_sizes, int n_in,
                              void* d_out, int out_size) {
    const float* input  = (const float*)d_in[0];
    const float* memory = (const float*)d_in[1];
    const float* wq = (const float*)d_in[2];
    const float* bq = (const float*)d_in[3];
    const float* wk = (const float*)d_in[4];
    const float* bk = (const float*)d_in[5];
    const float* wv = (const float*)d_in[6];
    const float* bv = (const float*)d_in[7];
    float* out = (float*)d_out;

    cudaFuncSetAttribute((const void*)convqk_k,
                         cudaFuncAttributeMaxDynamicSharedMemorySize, SMEMSZ3);
    cudaFuncSetAttribute((const void*)convv_k,
                         cudaFuncAttributeMaxDynamicSharedMemorySize, SMEMSZ1);
    cudaFuncSetAttribute((const void*)logits2_k,
                         cudaFuncAttributeMaxDynamicSharedMemorySize, LSMEMSZ);
    cudaFuncSetAttribute((const void*)out2_k,
                         cudaFuncAttributeMaxDynamicSharedMemorySize, OSMEM);

    pack_k<<<dim3(BB * LL, 16, 2), 256>>>(input, memory);
    wprep_k<<<(368640 + 255) / 256, 256>>>(wq, wk, wv);

    convqk_k<<<dim3(8, BB * LL), 128, SMEMSZ3>>>(bq, 0, 0.5f);
    convqk_k<<<dim3(8, BB * LL), 128, SMEMSZ3>>>(bk, 1, 1.0f);
    convv_k<<<dim3(8, BB * LV), 256, SMEMSZ1>>>(bv);

    logits2_k<<<dim3(9, 16), 256, LSMEMSZ>>>();
    softmax_k<<<256, 256>>>();
    out2_k<<<dim3(128, 8), 256, OSMEM>>>(out);
}

// round 14
// speedup vs baseline: 1.0601x; 1.0078x over previous
#include <cuda_runtime.h>
#include <cuda_fp16.h>
#include <cstdint>

#define BB   8
#define CIN  64
#define CO   128
#define LL   18
#define LV   16
#define HW   1024
#define NH   2

// ---------------- scratch (device globals; no allocation allowed) ----------
__device__ float g_lp[(size_t)9*BB*NH*CO*CO];

__device__ __half g_Qh[(size_t)BB*CO*LL*HW];
__device__ __half g_Ql[(size_t)BB*CO*LL*HW];
__device__ __half g_Kh[(size_t)BB*CO*LL*HW];
__device__ __half g_Kl[(size_t)BB*CO*LL*HW];
__device__ __half g_Vh[(size_t)BB*CO*LV*HW];
__device__ __half g_aH[(size_t)BB*NH*CO*CO];
__device__ __half g_aL[(size_t)BB*NH*CO*CO];

__device__ __half g_hin[(size_t)BB*LL*HW*CIN];
__device__ __half g_lin[(size_t)BB*LL*HW*CIN];
__device__ __half g_hmm[(size_t)BB*LL*HW*CIN];
__device__ __half g_lmm[(size_t)BB*LL*HW*CIN];

// weight images, 32-ci sub-chunks, pitch 40 halves: [sc][co=128][40]
__device__ uint4 g_wqh[18*640], g_wql[18*640];
__device__ uint4 g_wkh[18*640], g_wkl[18*640];
__device__ uint4 g_wvh[54*640], g_wvl[54*640];

// ---------------- PTX helpers ----------------------------------------------
__device__ __forceinline__ uint32_t smem_u32(const void* p) {
    uint32_t a;
    asm("{ .reg .u64 t; cvta.to.shared.u64 t, %1; cvt.u32.u64 %0, t; }"
        : "=r"(a) : "l"(p));
    return a;
}
__device__ __forceinline__ void ldmat4(uint32_t& r0, uint32_t& r1, uint32_t& r2,
                                       uint32_t& r3, uint32_t a) {
    asm volatile("ldmatrix.sync.aligned.m8n8.x4.shared.b16 {%0,%1,%2,%3}, [%4];"
                 : "=r"(r0), "=r"(r1), "=r"(r2), "=r"(r3) : "r"(a));
}
__device__ __forceinline__ void ldmat2t(uint32_t& r0, uint32_t& r1, uint32_t a) {
    asm volatile("ldmatrix.sync.aligned.m8n8.x2.trans.shared.b16 {%0,%1}, [%2];"
                 : "=r"(r0), "=r"(r1) : "r"(a));
}
__device__ __forceinline__ void mma16816(float* c, const uint32_t* a,
                                         const uint32_t* b) {
    asm volatile(
        "mma.sync.aligned.m16n8k16.row.col.f32.f16.f16.f32 "
        "{%0,%1,%2,%3}, {%4,%5,%6,%7}, {%8,%9}, {%0,%1,%2,%3};"
        : "+f"(c[0]), "+f"(c[1]), "+f"(c[2]), "+f"(c[3])
        : "r"(a[0]), "r"(a[1]), "r"(a[2]), "r"(a[3]), "r"(b[0]), "r"(b[1]));
}
__device__ __forceinline__ void cpasync16(uint32_t dst, const void* src, int sz) {
    asm volatile("cp.async.ca.shared.global [%0], [%1], 16, %2;"
                 :: "r"(dst), "l"(src), "r"(sz) : "memory");
}
__device__ __forceinline__ void cp_commit() {
    asm volatile("cp.async.commit_group;" ::: "memory");
}
__device__ __forceinline__ void cp_wait2() {
    asm volatile("cp.async.wait_group 2;" ::: "memory");
}
__device__ __forceinline__ void cp_wait1() {
    asm volatile("cp.async.wait_group 1;" ::: "memory");
}
__device__ __forceinline__ void cp_wait0() {
    asm volatile("cp.async.wait_group 0;" ::: "memory");
}

__device__ __forceinline__ void emit_split(__half* ph, __half* pl,
                                           float x, float y) {
    __half2 h, l;
    h.x = __float2half_rn(x);
    h.y = __float2half_rn(y);
    l.x = __float2half_rn(x - __half2float(h.x));
    l.y = __float2half_rn(y - __half2float(h.y));
    *(__half2*)ph = h;
    *(__half2*)pl = l;
}

// ---------------- prep kernels ---------------------------------------------
__global__ __launch_bounds__(256) void pack_k(const float* __restrict__ x0,
                                              const float* __restrict__ x1) {
    __shared__ float tile[64][65];
    const int s = blockIdx.x;
    const int hw0 = blockIdx.y * 64;
    const int dst = blockIdx.z;
    const int b = s / LL, l = s % LL;
    const float* x = dst ? x1 : x0;
    __half* oh = dst ? g_hmm : g_hin;
    __half* ol = dst ? g_lmm : g_lin;
#pragma unroll
    for (int i = 0; i < 16; i++) {
        int idx = threadIdx.x + i * 256;
        int ci = idx >> 6, hw = idx & 63;
        tile[ci][hw] = x[(((size_t)b * CIN + ci) * LL + l) * HW + hw0 + hw];
    }
    __syncthreads();
#pragma unroll
    for (int i = 0; i < 16; i++) {
        int idx = threadIdx.x + i * 256;
        int hw = idx >> 6, ci = idx & 63;
        float v = tile[ci][hw];
        __half h = __float2half_rn(v);
        size_t o = ((size_t)s * HW + hw0 + hw) * CIN + ci;
        oh[o] = h;
        ol[o] = __float2half_rn(v - __half2float(h));
    }
}

__global__ __launch_bounds__(256) void wprep_k(const float* __restrict__ wq,
                                               const float* __restrict__ wk,
                                               const float* __restrict__ wv) {
    int i = blockIdx.x * 256 + threadIdx.x;
    if (i >= 368640) return;
    const float* w;
    __half *oh, *ol;
    int ntap;
    if (i < 18 * 4096)       { w = wq; oh = (__half*)g_wqh; ol = (__half*)g_wql;
                               ntap = 9; }
    else if (i < 36 * 4096)  { w = wk; oh = (__half*)g_wkh; ol = (__half*)g_wkl;
                               ntap = 9; i -= 18 * 4096; }
    else                     { w = wv; oh = (__half*)g_wvh; ol = (__half*)g_wvl;
                               ntap = 27; i -= 36 * 4096; }
    int sc = i >> 12, r = i & 4095, co = r >> 5, ci32 = r & 31;
    int tap = sc >> 1, chalf = sc & 1;
    int ci = chalf * 32 + ci32;
    float v = w[(co * 64 + ci) * ntap + tap];
    __half h = __float2half_rn(v);
    __half lo = __float2half_rn(v - __half2float(h));
    oh[(size_t)sc * 5120 + co * 40 + ci32] = h;
    ol[(size_t)sc * 5120 + co * 40 + ci32] = lo;
}

// ------ Q/K conv: 3-pass, 128 threads, 64x64 warp tiles, 2 CTAs/SM ---------
// fused: blockIdx.z = 0 -> Q, 1 -> K
#define SMEMSZ3 81920   // 2-stage x 40960

__device__ __forceinline__ void issue_qk(
    int sc, int p0, int b, int l, uint32_t sb,
    const uint4* wh, const uint4* wl,
    const __half* xh, const __half* xl, int tid) {
    const int tap = sc >> 1, chalf = sc & 1;
    const int kh = tap / 3, kw = tap % 3;
    const uint32_t base = sb + (uint32_t)(sc & 1) * 40960u;
#pragma unroll
    for (int i = 0; i < 10; i++) {
        int idx = tid + i * 128;
        if (idx < 1280) {
            int hf = idx >= 640;
            int r = idx - hf * 640;
            const uint4* s = (hf ? wl : wh) + (size_t)sc * 640 + r;
            cpasync16(base + hf * 10240 + r * 16, s, 16);
        }
    }
    {
        int row = tid;
        int pg = p0 + row;
        int ih = (pg >> 5) + kh - 1, iw = (pg & 31) + kw - 1;
        int ok = ((unsigned)ih < 32u) && ((unsigned)iw < 32u);
        int ihc = ok ? ih : 0, iwc = ok ? iw : 0;
        size_t soff = ((size_t)((b * LL + l) * HW) + ihc * 32 + iwc) * CIN +
                      chalf * 32;
        int sz = ok ? 16 : 0;
        const __half* s0 = xh + soff;
        uint32_t d0 = base + 20480u + row * 80;
#pragma unroll
        for (int j = 0; j < 4; j++)
            cpasync16(d0 + j * 16, (const char*)s0 + j * 16, sz);
        const __half* s1 = xl + soff;
        uint32_t d1 = d0 + 10240;
#pragma unroll
        for (int j = 0; j < 4; j++)
            cpasync16(d1 + j * 16, (const char*)s1 + j * 16, sz);
    }
    cp_commit();
}

__global__ __launch_bounds__(128, 2)
void convqk_k(const float* __restrict__ bq, const float* __restrict__ bk) {
    extern __shared__ char smem[];
    const uint32_t sb = smem_u32(smem);
    const int tid = threadIdx.x, wid = tid >> 5, lane = tid & 31;
    const int p0 = blockIdx.x * 128;
    const int b = blockIdx.y / LL, l = blockIdx.y % LL;
    const int mode = blockIdx.z;

    const __half *xh, *xl;
    const uint4 *wh, *wl;
    __half *oph, *opl;
    const float* bias;
    float scale;
    if (mode == 0) { xh = g_hin; xl = g_lin; wh = g_wqh; wl = g_wql;
                     oph = g_Qh; opl = g_Ql; bias = bq; scale = 0.5f; }
    else           { xh = g_hmm; xl = g_lmm; wh = g_wkh; wl = g_wkl;
                     oph = g_Kh; opl = g_Kl; bias = bk; scale = 1.0f; }

    const int co0 = (wid & 1) * 64;
    const int p0l = (wid >> 1) * 64;
    const int bnt = (lane >> 4) & 1;
    const int bkh = (lane >> 3) & 1;

    float acc[4][8][4];
#pragma unroll
    for (int mt = 0; mt < 4; mt++)
#pragma unroll
        for (int nt = 0; nt < 8; nt++)
#pragma unroll
            for (int i = 0; i < 4; i++) acc[mt][nt][i] = 0.f;

    issue_qk(0, p0, b, l, sb, wh, wl, xh, xl, tid);
    issue_qk(1, p0, b, l, sb, wh, wl, xh, xl, tid);

    for (int sc = 0; sc < 18; sc++) {
        if (sc + 1 < 18) cp_wait1(); else cp_wait0();
        __syncthreads();
        const uint32_t base = sb + (uint32_t)(sc & 1) * 40960u;
        const uint32_t aAh = base, aAl = base + 10240;
        const uint32_t aBh = base + 20480u, aBl = base + 30720u;
#pragma unroll
        for (int k = 0; k < 2; k++) {
            uint32_t bh[8][2], bl[8][2];
#pragma unroll
            for (int pr = 0; pr < 4; pr++) {
                uint32_t off = (uint32_t)(((p0l + (pr * 2 + bnt) * 8 + (lane & 7)) * 40 +
                                           k * 16 + bkh * 8) * 2);
                ldmat4(bh[pr * 2][0], bh[pr * 2][1],
                       bh[pr * 2 + 1][0], bh[pr * 2 + 1][1], aBh + off);
                ldmat4(bl[pr * 2][0], bl[pr * 2][1],
                       bl[pr * 2 + 1][0], bl[pr * 2 + 1][1], aBl + off);
            }
            uint32_t a[4][4];
#pragma unroll
            for (int mt = 0; mt < 4; mt++) {
                uint32_t off = (uint32_t)(((co0 + mt * 16 + (lane & 15)) * 40 +
                                           k * 16 + (lane >> 4) * 8) * 2);
                ldmat4(a[mt][0], a[mt][1], a[mt][2], a[mt][3], aAh + off);
            }
#pragma unroll
            for (int mt = 0; mt < 4; mt++)
#pragma unroll
                for (int nt = 0; nt < 8; nt++)
                    mma16816(acc[mt][nt], a[mt], bh[nt]);
#pragma unroll
            for (int mt = 0; mt < 4; mt++)
#pragma unroll
                for (int nt = 0; nt < 8; nt++)
                    mma16816(acc[mt][nt], a[mt], bl[nt]);
#pragma unroll
            for (int mt = 0; mt < 4; mt++) {
                uint32_t off = (uint32_t)(((co0 + mt * 16 + (lane & 15)) * 40 +
                                           k * 16 + (lane >> 4) * 8) * 2);
                ldmat4(a[mt][0], a[mt][1], a[mt][2], a[mt][3], aAl + off);
            }
#pragma unroll
            for (int mt = 0; mt < 4; mt++)
#pragma unroll
                for (int nt = 0; nt < 8; nt++)
                    mma16816(acc[mt][nt], a[mt], bh[nt]);
        }
        __syncthreads();
        if (sc + 2 < 18)
            issue_qk(sc + 2, p0, b, l, sb, wh, wl, xh, xl, tid);
    }

#pragma unroll
    for (int mt = 0; mt < 4; mt++) {
        int co = co0 + mt * 16 + (lane >> 2);
        float bv0 = bias[co];
        float bv1 = bias[co + 8];
        size_t o0 = ((size_t)(b * CO + co) * LL + l) * HW + p0 + p0l;
        size_t o1 = o0 + (size_t)8 * LL * HW;
#pragma unroll
        for (int nt = 0; nt < 8; nt++) {
            int p = nt * 8 + (lane & 3) * 2;
            emit_split(oph + o0 + p, opl + o0 + p,
                       (acc[mt][nt][0] + bv0) * scale,
                       (acc[mt][nt][1] + bv0) * scale);
            emit_split(oph + o1 + p, opl + o1 + p,
                       (acc[mt][nt][2] + bv1) * scale,
                       (acc[mt][nt][3] + bv1) * scale);
        }
    }
}

// ------ V conv: 1-pass, 256 threads, 64x32 tiles, 4-stage, 2 CTAs/SM -------
#define SMEMSZ1 81920   // 4-stage x 20480

__device__ __forceinline__ void issue_v(
    int sc, int p0, int b, int l, uint32_t sb,
    const uint4* wh, const __half* xh, int tid) {
    const int tap = sc >> 1, chalf = sc & 1;
    const int kd = tap / 9;
    const int r9 = tap % 9;
    const int kh = r9 / 3, kw = r9 % 3;
    const uint32_t base = sb + (uint32_t)(sc & 3) * 20480u;
#pragma unroll
    for (int i = 0; i < 3; i++) {
        int idx = tid + i * 256;
        if (idx < 640) {
            const uint4* s = wh + (size_t)sc * 640 + idx;
            cpasync16(base + idx * 16, s, 16);
        }
    }
    {
        int row = tid >> 1;
        int j0 = (tid & 1) * 2;
        int pg = p0 + row;
        int ih = (pg >> 5) + kh - 1, iw = (pg & 31) + kw - 1;
        int ok = ((unsigned)ih < 32u) && ((unsigned)iw < 32u);
        int ihc = ok ? ih : 0, iwc = ok ? iw : 0;
        const __half* s = xh +
            ((size_t)((b * LL + l + kd) * HW) + ihc * 32 + iwc) * CIN + chalf * 32;
        uint32_t dst = base + 10240u + row * 80;
        int sz = ok ? 16 : 0;
#pragma unroll
        for (int j = 0; j < 2; j++)
            cpasync16(dst + (j0 + j) * 16, (const char*)s + (j0 + j) * 16, sz);
    }
    cp_commit();
}

__global__ __launch_bounds__(256, 2)
void convv_k(const float* __restrict__ bias) {
    extern __shared__ char smem[];
    const uint32_t sb = smem_u32(smem);
    const int tid = threadIdx.x, wid = tid >> 5, lane = tid & 31;
    const int p0 = blockIdx.x * 128;
    const int b = blockIdx.y / LV, l = blockIdx.y % LV;

    const int co0 = (wid & 1) * 64;
    const int p0l = (wid >> 1) * 32;
    const int bnt = (lane >> 4) & 1;
    const int bkh = (lane >> 3) & 1;

    float acc[4][4][4];
#pragma unroll
    for (int mt = 0; mt < 4; mt++)
#pragma unroll
        for (int nt = 0; nt < 4; nt++)
#pragma unroll
            for (int i = 0; i < 4; i++) acc[mt][nt][i] = 0.f;

    issue_v(0, p0, b, l, sb, g_wvh, g_hmm, tid);
    issue_v(1, p0, b, l, sb, g_wvh, g_hmm, tid);
    issue_v(2, p0, b, l, sb, g_wvh, g_hmm, tid);

    for (int sc = 0; sc < 54; sc++) {
        if (sc < 52)      cp_wait2();
        else if (sc < 53) cp_wait1();
        else              cp_wait0();
        __syncthreads();
        const uint32_t base = sb + (uint32_t)(sc & 3) * 20480u;
        const uint32_t aAh = base;
        const uint32_t aBh = base + 10240u;
#pragma unroll
        for (int k = 0; k < 2; k++) {
            uint32_t bh[4][2];
#pragma unroll
            for (int pr = 0; pr < 2; pr++) {
                uint32_t off = (uint32_t)(((p0l + (pr * 2 + bnt) * 8 + (lane & 7)) * 40 +
                                           k * 16 + bkh * 8) * 2);
                ldmat4(bh[pr * 2][0], bh[pr * 2][1],
                       bh[pr * 2 + 1][0], bh[pr * 2 + 1][1], aBh + off);
            }
            uint32_t a[4][4];
#pragma unroll
            for (int mt = 0; mt < 4; mt++) {
                uint32_t off = (uint32_t)(((co0 + mt * 16 + (lane & 15)) * 40 +
                                           k * 16 + (lane >> 4) * 8) * 2);
                ldmat4(a[mt][0], a[mt][1], a[mt][2], a[mt][3], aAh + off);
            }
#pragma unroll
            for (int mt = 0; mt < 4; mt++)
#pragma unroll
                for (int nt = 0; nt < 4; nt++)
                    mma16816(acc[mt][nt], a[mt], bh[nt]);
        }
        if (sc + 3 < 54)
            issue_v(sc + 3, p0, b, l, sb, g_wvh, g_hmm, tid);
    }

#pragma unroll
    for (int mt = 0; mt < 4; mt++) {
        int co = co0 + mt * 16 + (lane >> 2);
        float bv0 = bias[co];
        float bv1 = bias[co + 8];
        size_t o0 = ((size_t)(b * CO + co) * LV + l) * HW + p0 + p0l;
        size_t o1 = o0 + (size_t)8 * LV * HW;
#pragma unroll
        for (int nt = 0; nt < 4; nt++) {
            int p = nt * 8 + (lane & 3) * 2;
            __half2 v0, v1;
            v0.x = __float2half_rn(acc[mt][nt][0] + bv0);
            v0.y = __float2half_rn(acc[mt][nt][1] + bv0);
            v1.x = __float2half_rn(acc[mt][nt][2] + bv1);
            v1.y = __float2half_rn(acc[mt][nt][3] + bv1);
            *(__half2*)(g_Vh + o0 + p) = v0;
            *(__half2*)(g_Vh + o1 + p) = v1;
        }
    }
}

// ---------------- logits: Q.K^T via HMMA, split-K over 9 l-slices ----------
#define LAB  18432
#define LBUF 73728
#define LSMEMSZ (2*LBUF)

__global__ __launch_bounds__(256, 1) void logits2_k() {
    extern __shared__ char smem[];
    const uint32_t sb = smem_u32(smem);
    const int tid = threadIdx.x, wid = tid >> 5, lane = tid & 31;
    const int lc = blockIdx.x, bn = blockIdx.y;
    const int b = bn >> 1, n = bn & 1;
    const int l = n * 9 + lc;

    const __half* srcs[4];
    srcs[0] = g_Qh + ((size_t)(b * CO) * LL + l) * HW;
    srcs[1] = g_Ql + ((size_t)(b * CO) * LL + l) * HW;
    srcs[2] = g_Kh + ((size_t)(b * CO) * LL + l) * HW;
    srcs[3] = g_Kl + ((size_t)(b * CO) * LL + l) * HW;

    const int co0 = (wid & 1) * 64;
    const int p0l = (wid >> 1) * 32;
    const int bnt = (lane >> 4) & 1;
    const int bkh = (lane >> 3) & 1;

    float acc[4][4][4];
#pragma unroll
    for (int mt = 0; mt < 4; mt++)
#pragma unroll
        for (int nt = 0; nt < 4; nt++)
#pragma unroll
            for (int i = 0; i < 4; i++) acc[mt][nt][i] = 0.f;

    auto issue = [&](int ch) {
        const uint32_t base = sb + (ch & 1) * LBUF;
        const int hw0 = ch * 64;
#pragma unroll
        for (int r = tid; r < 512; r += 256) {
            int plane = r >> 7, c = r & 127;
            const __half* s = srcs[plane] + (size_t)c * (LL * HW) + hw0;
            uint32_t dst = base + plane * LAB + c * 144;
#pragma unroll
            for (int j = 0; j < 8; j++)
                cpasync16(dst + j * 16, (const char*)s + j * 16, 16);
        }
        cp_commit();
    };

    issue(0);
    for (int ch = 0; ch < 16; ch++) {
        if (ch + 1 < 16) { issue(ch + 1); cp_wait1(); }
        else             { cp_wait0(); }
        __syncthreads();
        const uint32_t base = sb + (ch & 1) * LBUF;
        const uint32_t aAh = base, aAl = base + LAB;
        const uint32_t aBh = base + 2 * LAB, aBl = base + 3 * LAB;
#pragma unroll
        for (int k = 0; k < 4; k++) {
            uint32_t bh[4][2], bl[4][2];
#pragma unroll
            for (int pr = 0; pr < 2; pr++) {
                uint32_t off = (uint32_t)(((p0l + (pr * 2 + bnt) * 8 + (lane & 7)) * 72 +
                                           k * 16 + bkh * 8) * 2);
                ldmat4(bh[pr * 2][0], bh[pr * 2][1],
                       bh[pr * 2 + 1][0], bh[pr * 2 + 1][1], aBh + off);
                ldmat4(bl[pr * 2][0], bl[pr * 2][1],
                       bl[pr * 2 + 1][0], bl[pr * 2 + 1][1], aBl + off);
            }
            uint32_t a[4][4];
#pragma unroll
            for (int mt = 0; mt < 4; mt++) {
                uint32_t off = (uint32_t)(((co0 + mt * 16 + (lane & 15)) * 72 +
                                           k * 16 + (lane >> 4) * 8) * 2);
                ldmat4(a[mt][0], a[mt][1], a[mt][2], a[mt][3], aAh + off);
            }
#pragma unroll
            for (int mt = 0; mt < 4; mt++)
#pragma unroll
                for (int nt = 0; nt < 4; nt++)
                    mma16816(acc[mt][nt], a[mt], bh[nt]);
#pragma unroll
            for (int mt = 0; mt < 4; mt++)
#pragma unroll
                for (int nt = 0; nt < 4; nt++)
                    mma16816(acc[mt][nt], a[mt], bl[nt]);
#pragma unroll
            for (int mt = 0; mt < 4; mt++) {
                uint32_t off = (uint32_t)(((co0 + mt * 16 + (lane & 15)) * 72 +
                                           k * 16 + (lane >> 4) * 8) * 2);
                ldmat4(a[mt][0], a[mt][1], a[mt][2], a[mt][3], aAl + off);
            }
#pragma unroll
            for (int mt = 0; mt < 4; mt++)
#pragma unroll
                for (int nt = 0; nt < 4; nt++)
                    mma16816(acc[mt][nt], a[mt], bh[nt]);
        }
        __syncthreads();
    }

    float* lp = g_lp + ((size_t)lc * 16 + bn) * CO * CO;
#pragma unroll
    for (int mt = 0; mt < 4; mt++) {
        int c = co0 + mt * 16 + (lane >> 2);
#pragma unroll
        for (int nt = 0; nt < 4; nt++) {
            int m = p0l + nt * 8 + (lane & 3) * 2;
            *(float2*)(lp + (size_t)c * CO + m) =
                make_float2(acc[mt][nt][0], acc[mt][nt][1]);
            *(float2*)(lp + (size_t)(c + 8) * CO + m) =
                make_float2(acc[mt][nt][2], acc[mt][nt][3]);
        }
    }
}

// ---------------- softmax ---------------------------------------------------
__global__ __launch_bounds__(256) void softmax_k() {
    const int warp = (blockIdx.x * 256 + threadIdx.x) >> 5;
    const int lane = threadIdx.x & 31;
    if (warp >= 16 * CO) return;
    const int bn = warp >> 7, c = warp & 127;
    float v[4];
#pragma unroll
    for (int j = 0; j < 4; j++) {
        int m = lane + j * 32;
        float s = 0.f;
#pragma unroll
        for (int p = 0; p < 9; p++)
            s += g_lp[(((size_t)p * 16 + bn) * CO + c) * CO + m];
        v[j] = s;
    }
    float mx = fmaxf(fmaxf(v[0], v[1]), fmaxf(v[2], v[3]));
#pragma unroll
    for (int o = 16; o; o >>= 1) mx = fmaxf(mx, __shfl_xor_sync(0xffffffffu, mx, o));
    float sum = 0.f;
#pragma unroll
    for (int j = 0; j < 4; j++) { v[j] = __expf(v[j] - mx); sum += v[j]; }
#pragma unroll
    for (int o = 16; o; o >>= 1) sum += __shfl_xor_sync(0xffffffffu, sum, o);
    float inv = 1.f / sum;
#pragma unroll
    for (int j = 0; j < 4; j++) {
        float a = v[j] * inv;
        __half h = __float2half_rn(a);
        size_t o = ((size_t)bn * CO + c) * CO + lane + j * 32;
        g_aH[o] = h;
        g_aL[o] = __float2half_rn(a - __half2float(h));
    }
}

// ---------------- out: attn(hi,lo) x V(fp16) via HMMA, 2 passes ------------
#define OPITCH 272
#define OTILE  34816
#define OSMEM  (3*OTILE)

__global__ __launch_bounds__(256, 1) void out2_k(float* __restrict__ out) {
    extern __shared__ char smem[];
    const uint32_t sb = smem_u32(smem);
    const int tid = threadIdx.x, wid = tid >> 5, lane = tid & 31;
    const int pt = blockIdx.x, b = blockIdx.y;
    const int l = pt >> 3;
    const int hw0 = (pt & 7) * 128;
    const int bn = b * 2 + (l >> 3);

    {
        int c = tid & 127;
        if (tid < 128) {
            const __half* s = g_aH + ((size_t)bn * CO + c) * CO;
            uint32_t dst = sb + c * OPITCH;
#pragma unroll
            for (int j = 0; j < 16; j++)
                cpasync16(dst + j * 16, (const char*)s + j * 16, 16);
            const __half* sv = g_Vh + ((size_t)(b * CO + c) * LV + l) * HW + hw0;
            uint32_t dv = sb + 2 * OTILE + c * OPITCH;
#pragma unroll
            for (int j = 0; j < 16; j++)
                cpasync16(dv + j * 16, (const char*)sv + j * 16, 16);
        } else {
            const __half* s = g_aL + ((size_t)bn * CO + c) * CO;
            uint32_t dst = sb + OTILE + c * OPITCH;
#pragma unroll
            for (int j = 0; j < 16; j++)
                cpasync16(dst + j * 16, (const char*)s + j * 16, 16);
        }
    }
    cp_commit();
    cp_wait0();
    __syncthreads();

    const int co0 = (wid & 1) * 64;
    const int p0l = (wid >> 1) * 32;
    const uint32_t aAh = sb, aAl = sb + OTILE;
    const uint32_t aB = sb + 2 * OTILE;

    float acc[4][4][4];
#pragma unroll
    for (int mt = 0; mt < 4; mt++)
#pragma unroll
        for (int nt = 0; nt < 4; nt++)
#pragma unroll
            for (int i = 0; i < 4; i++) acc[mt][nt][i] = 0.f;

#pragma unroll
    for (int kc = 0; kc < 8; kc++) {
        uint32_t bh[4][2];
#pragma unroll
        for (int nt = 0; nt < 4; nt++) {
            uint32_t off = (uint32_t)((kc * 16 + (lane & 15)) * OPITCH +
                                      (p0l + nt * 8) * 2);
            ldmat2t(bh[nt][0], bh[nt][1], aB + off);
        }
        uint32_t a[4][4];
#pragma unroll
        for (int mt = 0; mt < 4; mt++) {
            uint32_t off = (uint32_t)((co0 + mt * 16 + (lane & 15)) * OPITCH +
                                      kc * 32 + (lane >> 4) * 16);
            ldmat4(a[mt][0], a[mt][1], a[mt][2], a[mt][3], aAh + off);
        }
#pragma unroll
        for (int mt = 0; mt < 4; mt++)
#pragma unroll
            for (int nt = 0; nt < 4; nt++)
                mma16816(acc[mt][nt], a[mt], bh[nt]);
#pragma unroll
        for (int mt = 0; mt < 4; mt++) {
            uint32_t off = (uint32_t)((co0 + mt * 16 + (lane & 15)) * OPITCH +
                                      kc * 32 + (lane >> 4) * 16);
            ldmat4(a[mt][0], a[mt][1], a[mt][2], a[mt][3], aAl + off);
        }
#pragma unroll
        for (int mt = 0; mt < 4; mt++)
#pragma unroll
            for (int nt = 0; nt < 4; nt++)
                mma16816(acc[mt][nt], a[mt], bh[nt]);
    }

#pragma unroll
    for (int mt = 0; mt < 4; mt++) {
        int c = co0 + mt * 16 + (lane >> 2);
        float* o0 = out + ((size_t)(b * CO + c) * LV + l) * HW + hw0 + p0l;
        float* o1 = o0 + (size_t)8 * LV * HW;
#pragma unroll
        for (int nt = 0; nt < 4; nt++) {
            int p = nt * 8 + (lane & 3) * 2;
            *(float2*)(o0 + p) = make_float2(acc[mt][nt][0], acc[mt][nt][1]);
            *(float2*)(o1 + p) = make_float2(acc[mt][nt][2], acc[mt][nt][3]);
        }
    }
}

// ---------------------------------------------------------------------------
extern "C" void kernel_launch(void* const* d_in, const int* in_sizes, int n_in,
                              void* d_out, int out_size) {
    const float* input  = (const float*)d_in[0];
    const float* memory = (const float*)d_in[1];
    const float* wq = (const float*)d_in[2];
    const float* bq = (const float*)d_in[3];
    const float* wk = (const float*)d_in[4];
    const float* bk = (const float*)d_in[5];
    const float* wv = (const float*)d_in[6];
    const float* bv = (const float*)d_in[7];
    float* out = (float*)d_out;

    cudaFuncSetAttribute((const void*)convqk_k,
                         cudaFuncAttributeMaxDynamicSharedMemorySize, SMEMSZ3);
    cudaFuncSetAttribute((const void*)convv_k,
                         cudaFuncAttributeMaxDynamicSharedMemorySize, SMEMSZ1);
    cudaFuncSetAttribute((const void*)logits2_k,
                         cudaFuncAttributeMaxDynamicSharedMemorySize, LSMEMSZ);
    cudaFuncSetAttribute((const void*)out2_k,
                         cudaFuncAttributeMaxDynamicSharedMemorySize, OSMEM);

    pack_k<<<dim3(BB * LL, 16, 2), 256>>>(input, memory);
    wprep_k<<<(368640 + 255) / 256, 256>>>(wq, wk, wv);

    convqk_k<<<dim3(8, BB * LL, 2), 128, SMEMSZ3>>>(bq, bk);
    convv_k<<<dim3(8, BB * LV), 256, SMEMSZ1>>>(bv);

    logits2_k<<<dim3(9, 16), 256, LSMEMSZ>>>();
    softmax_k<<<256, 256>>>();
    out2_k<<<dim3(128, 8), 256, OSMEM>>>(out);
}